// round 12
// baseline (speedup 1.0000x reference)
#include <cuda_runtime.h>
#include <cstdint>

#define BB 2
#define TT 2048
#define DD 1024
#define HH 16
#define DKK 64
#define BT 4096   // BB*TT

// ---------------- scratch (device globals; no runtime allocation) -------------
__device__ float g_q[(size_t)BT * DD];
__device__ float g_k[(size_t)BT * DD];
__device__ float g_v[(size_t)BT * DD];
__device__ float g_x[(size_t)BT * DD];
__device__ float g_o[(size_t)BT * DD];
__device__ float2 g_stats[(size_t)BB * HH * TT];   // per (z,row): {raw max, sum exp}
// fallback attn scratch in case d_out only holds y (tuple handling safety)
__device__ float g_attn_scratch[(size_t)BB * HH * TT * TT];

// ----------------------------- helpers ---------------------------------------
__device__ __forceinline__ unsigned f2tf32(float x) {
    unsigned u;
    asm("cvt.rna.tf32.f32 %0, %1;" : "=r"(u) : "f"(x));
    return u;
}

__device__ __forceinline__ float ex2f(float x) {
    float r;
    asm("ex2.approx.ftz.f32 %0, %1;" : "=f"(r) : "f"(x));
    return r;
}

__device__ __forceinline__ void mma_tf32(float c[4], const unsigned a[4], const unsigned b[2]) {
    asm volatile(
        "mma.sync.aligned.m16n8k8.row.col.f32.tf32.tf32.f32 "
        "{%0,%1,%2,%3}, {%4,%5,%6,%7}, {%8,%9}, {%0,%1,%2,%3};"
        : "+f"(c[0]), "+f"(c[1]), "+f"(c[2]), "+f"(c[3])
        : "r"(a[0]), "r"(a[1]), "r"(a[2]), "r"(a[3]), "r"(b[0]), "r"(b[1]));
}

__device__ __forceinline__ void cpa16(uint32_t dst, const float* src) {
    asm volatile("cp.async.cg.shared.global [%0], [%1], 16;" :: "r"(dst), "l"(src));
}

// =============================================================================
// NT tf32 GEMM, cp.async 3-stage pipeline. C[m,n] = sum_k A[m,k]*B[n,k] + bias.
// Tile 128x128, BK=32, 256 threads, 2 CTAs/SM, ONE barrier per k-iteration.
// fp32 staged in smem; RNA tf32 cvt after fragment LDS (identical numerics).
// =============================================================================
#define SKA 36        // smem row stride (floats) for 128x32 tiles
#define STAGE_ELE (2 * 128 * SKA)   // A tile + B tile, floats
#define MMA_NT_SMEM (3 * STAGE_ELE * 4)

__global__ __launch_bounds__(256, 2)
void mma_nt(const float* __restrict__ A, int lda,
            const float* __restrict__ Bm, int ldb,
            float* __restrict__ C, int ldc,
            const float* __restrict__ bias, int K, float alpha)
{
    extern __shared__ float smp[];   // 3 stages x (A[128][36] + B[128][36])

    int tid = threadIdx.x;
    int lane = tid & 31, wid = tid >> 5;
    int g = lane >> 2, tg = lane & 3;
    int wm = (wid & 1) * 64;
    int wn = (wid >> 1) * 32;

    int bm = blockIdx.y * 128;
    int bn = blockIdx.x * 128;

    // loader: 2 threads per row; each does 4x cp.async 16B per tile
    int lrow = tid >> 1;            // 0..127
    int lc   = (tid & 1) * 16;      // float offset 0 or 16

    const float* Ag = A  + (long)(bm + lrow) * lda + lc;
    const float* Bg = Bm + (long)(bn + lrow) * ldb + lc;

    uint32_t sbase = (uint32_t)__cvta_generic_to_shared(smp);
    uint32_t dA = sbase + (lrow * SKA + lc) * 4;
    uint32_t dB = dA + 128 * SKA * 4;

    const int NT = K / 32;

    // prologue: issue tiles 0 and 1
#pragma unroll
    for (int t = 0; t < 2; t++) {
        uint32_t so = t * STAGE_ELE * 4;
        const float* ap = Ag + t * 32;
        const float* bp = Bg + t * 32;
#pragma unroll
        for (int i = 0; i < 4; i++) {
            cpa16(dA + so + i * 16, ap + i * 4);
            cpa16(dB + so + i * 16, bp + i * 4);
        }
        asm volatile("cp.async.commit_group;");
    }

    float acc[4][4][4];
#pragma unroll
    for (int i = 0; i < 4; i++)
#pragma unroll
        for (int j = 0; j < 4; j++)
#pragma unroll
            for (int r = 0; r < 4; r++) acc[i][j][r] = 0.0f;

    for (int kt = 0; kt < NT; kt++) {
        asm volatile("cp.async.wait_group 1;");
        __syncthreads();            // tile kt ready; all done computing kt-1

        // issue tile kt+2 into the slot freed by tile kt-1
        if (kt + 2 < NT) {
            int s = (kt + 2) % 3;
            uint32_t so = s * STAGE_ELE * 4;
            const float* ap = Ag + (kt + 2) * 32;
            const float* bp = Bg + (kt + 2) * 32;
#pragma unroll
            for (int i = 0; i < 4; i++) {
                cpa16(dA + so + i * 16, ap + i * 4);
                cpa16(dB + so + i * 16, bp + i * 4);
            }
        }
        asm volatile("cp.async.commit_group;");   // always (keeps group count in sync)

        const float* Asf = smp + (kt % 3) * STAGE_ELE;
        const float* Bsf = Asf + 128 * SKA;

#pragma unroll
        for (int ks = 0; ks < 4; ks++) {
            int kb = ks * 8;
            unsigned a[4][4], b[4][2];
#pragma unroll
            for (int mf = 0; mf < 4; mf++) {
                int m = wm + mf * 16;
                a[mf][0] = f2tf32(Asf[(m + g) * SKA + kb + tg]);
                a[mf][1] = f2tf32(Asf[(m + g + 8) * SKA + kb + tg]);
                a[mf][2] = f2tf32(Asf[(m + g) * SKA + kb + tg + 4]);
                a[mf][3] = f2tf32(Asf[(m + g + 8) * SKA + kb + tg + 4]);
            }
#pragma unroll
            for (int nf = 0; nf < 4; nf++) {
                int n = wn + nf * 8;
                b[nf][0] = f2tf32(Bsf[(n + g) * SKA + kb + tg]);
                b[nf][1] = f2tf32(Bsf[(n + g) * SKA + kb + tg + 4]);
            }
#pragma unroll
            for (int mf = 0; mf < 4; mf++)
#pragma unroll
                for (int nf = 0; nf < 4; nf++)
                    mma_tf32(acc[mf][nf], a[mf], b[nf]);
        }
    }

#pragma unroll
    for (int mf = 0; mf < 4; mf++) {
#pragma unroll
        for (int nf = 0; nf < 4; nf++) {
            int m0 = bm + wm + mf * 16 + g;
            int n0 = bn + wn + nf * 8 + 2 * tg;
            float b0 = bias ? bias[n0] : 0.0f;
            float b1 = bias ? bias[n0 + 1] : 0.0f;
            float* c0 = C + (long)m0 * ldc + n0;
            float* c1 = C + (long)(m0 + 8) * ldc + n0;
            c0[0] = alpha * acc[mf][nf][0] + b0;
            c0[1] = alpha * acc[mf][nf][1] + b1;
            c1[0] = alpha * acc[mf][nf][2] + b0;
            c1[1] = alpha * acc[mf][nf][3] + b1;
        }
    }
}

#define QS 68    // Qs/Ks stride (u32)
#define VS 72    // Vs stride
#define PS 132   // Ps stride
#define C1F 0.18033688f   // 0.125 * log2(e)

// =============================================================================
// Pass 1: row stats (identical to round-8 version). 2 CTAs/SM.
// =============================================================================
__global__ __launch_bounds__(256, 2)
void fstats(const float* __restrict__ Qg, const float* __restrict__ Kg,
            float2* __restrict__ stats)
{
    extern __shared__ unsigned sm1[];
    unsigned* Qs = sm1;                         // [128][QS]
    unsigned* Ks = Qs + 128 * QS;               // [128][QS]
    float* rmax = (float*)(Ks + 128 * QS);      // [4][128]
    float* rsum = rmax + 4 * 128;               // [4][128]

    int z = blockIdx.z, b = z >> 4, h = z & 15;
    int bm = blockIdx.y * 128;
    const float* Qz = Qg + ((long)b * TT + bm) * DD + h * DKK;
    const float* Kz = Kg + (long)b * TT * DD + h * DKK;

    int tid = threadIdx.x, lane = tid & 31, wid = tid >> 5;
    int g = lane >> 2, tg = lane & 3;
    int wm = (wid & 1) * 64, wn = (wid >> 1) * 32;
    int wnidx = wid >> 1;

    int lrow = tid >> 4;           // 0..15
    int lc4  = (tid & 15) * 4;     // 0..60

#pragma unroll
    for (int i = 0; i < 8; i++) {
        int row = lrow + i * 16;
        float4 qv = *(const float4*)(Qz + (long)row * DD + lc4);
        uint4 t = { f2tf32(qv.x), f2tf32(qv.y), f2tf32(qv.z), f2tf32(qv.w) };
        *(uint4*)(&Qs[row * QS + lc4]) = t;
    }

    float Mloc[4][2], Tloc[4][2];
#pragma unroll
    for (int mf = 0; mf < 4; mf++) {
        Mloc[mf][0] = Mloc[mf][1] = -1e30f;
        Tloc[mf][0] = Tloc[mf][1] = 0.0f;
    }

    for (int kt = 0; kt < 16; kt++) {
        __syncthreads();
#pragma unroll
        for (int i = 0; i < 8; i++) {
            int row = lrow + i * 16;
            float4 kv = *(const float4*)(Kz + (long)(kt * 128 + row) * DD + lc4);
            uint4 t = { f2tf32(kv.x), f2tf32(kv.y), f2tf32(kv.z), f2tf32(kv.w) };
            *(uint4*)(&Ks[row * QS + lc4]) = t;
        }
        __syncthreads();

        float acc[4][4][4];
#pragma unroll
        for (int i = 0; i < 4; i++)
#pragma unroll
            for (int j = 0; j < 4; j++)
#pragma unroll
                for (int r = 0; r < 4; r++) acc[i][j][r] = 0.0f;

#pragma unroll
        for (int ks = 0; ks < 8; ks++) {
            int kb = ks * 8;
            unsigned a[4][4], bf[4][2];
#pragma unroll
            for (int mf = 0; mf < 4; mf++) {
                int m = wm + mf * 16;
                a[mf][0] = Qs[(m + g) * QS + kb + tg];
                a[mf][1] = Qs[(m + g + 8) * QS + kb + tg];
                a[mf][2] = Qs[(m + g) * QS + kb + tg + 4];
                a[mf][3] = Qs[(m + g + 8) * QS + kb + tg + 4];
            }
#pragma unroll
            for (int nf = 0; nf < 4; nf++) {
                int n = wn + nf * 8;
                bf[nf][0] = Ks[(n + g) * QS + kb + tg];
                bf[nf][1] = Ks[(n + g) * QS + kb + tg + 4];
            }
#pragma unroll
            for (int mf = 0; mf < 4; mf++)
#pragma unroll
                for (int nf = 0; nf < 4; nf++)
                    mma_tf32(acc[mf][nf], a[mf], bf[nf]);
        }

#pragma unroll
        for (int mf = 0; mf < 4; mf++) {
#pragma unroll
            for (int nf = 0; nf < 4; nf++) {
                Mloc[mf][0] = fmaxf(Mloc[mf][0], fmaxf(acc[mf][nf][0], acc[mf][nf][1]));
                Mloc[mf][1] = fmaxf(Mloc[mf][1], fmaxf(acc[mf][nf][2], acc[mf][nf][3]));
                Tloc[mf][0] += ex2f(acc[mf][nf][0] * C1F) + ex2f(acc[mf][nf][1] * C1F);
                Tloc[mf][1] += ex2f(acc[mf][nf][2] * C1F) + ex2f(acc[mf][nf][3] * C1F);
            }
        }
    }

#pragma unroll
    for (int mf = 0; mf < 4; mf++)
#pragma unroll
        for (int i = 0; i < 2; i++) {
            float m = Mloc[mf][i], t = Tloc[mf][i];
#pragma unroll
            for (int sft = 1; sft <= 2; sft <<= 1) {
                m = fmaxf(m, __shfl_xor_sync(0xffffffffu, m, sft));
                t += __shfl_xor_sync(0xffffffffu, t, sft);
            }
            if (tg == 0) {
                int row = wm + mf * 16 + g + i * 8;
                rmax[wnidx * 128 + row] = m;
                rsum[wnidx * 128 + row] = t;
            }
        }
    __syncthreads();
    if (tid < 128) {
        float M = fmaxf(fmaxf(rmax[tid], rmax[128 + tid]),
                        fmaxf(rmax[256 + tid], rmax[384 + tid]));
        float T = rsum[tid] + rsum[128 + tid] + rsum[256 + tid] + rsum[384 + tid];
        stats[(long)z * TT + bm + tid] = make_float2(M, T);
    }
}

#define FSTATS_SMEM ((128 * QS * 2) * 4 + (4 * 128 * 2) * 4)

// =============================================================================
// Pass 2: recompute S, write NORMALIZED attn once, PV -> X.
// (identical to round-8 version — best measured)
// =============================================================================
__global__ __launch_bounds__(256, 1)
void fattn2(const float* __restrict__ Qg, const float* __restrict__ Kg,
            const float* __restrict__ Vg, const float2* __restrict__ stats,
            float* __restrict__ attn, float* __restrict__ Xg)
{
    extern __shared__ unsigned smem_u[];
    unsigned* Qs = smem_u;                          // [128][QS]
    unsigned* Ks = Qs + 128 * QS;                   // [128][QS]
    unsigned* Vs = Ks + 128 * QS;                   // [128][VS]
    unsigned* Ps = Vs + 128 * VS;                   // [128][PS]
    float* invr = (float*)(Ps + 128 * PS);          // [128]

    int z = blockIdx.z, b = z >> 4, h = z & 15;
    int bm = blockIdx.y * 128;
    const float* Qz = Qg + ((long)b * TT + bm) * DD + h * DKK;
    const float* Kz = Kg + (long)b * TT * DD + h * DKK;
    const float* Vz = Vg + (long)b * TT * DD + h * DKK;
    float* Az = attn + (long)z * TT * TT + (long)bm * TT;
    float* Xz = Xg + ((long)b * TT + bm) * DD + h * DKK;

    int tid = threadIdx.x, lane = tid & 31, wid = tid >> 5;
    int g = lane >> 2, tg = lane & 3;
    int wm = (wid & 1) * 64, wn = (wid >> 1) * 32;      // QK warp layout (2m x 4n)
    int wm2 = (wid >> 1) * 32, wn2 = (wid & 1) * 32;    // PV warp layout (4m x 2n)

    int lrow = tid >> 4;           // 0..15
    int lc4  = (tid & 15) * 4;     // 0..60

    // inv per row from stats
    if (tid < 128) {
        float2 st = stats[(long)z * TT + bm + tid];
        invr[tid] = 1.0f / (ex2f(st.x * C1F) + st.y);   // softmax-one denominator
    }

    // load Q tile -> Qs tf32
#pragma unroll
    for (int i = 0; i < 8; i++) {
        int row = lrow + i * 16;
        float4 qv = *(const float4*)(Qz + (long)row * DD + lc4);
        uint4 t = { f2tf32(qv.x), f2tf32(qv.y), f2tf32(qv.z), f2tf32(qv.w) };
        *(uint4*)(&Qs[row * QS + lc4]) = t;
    }

    // K/V register prefetch of tile 0
    float4 kb4[8], vb4[8];
#pragma unroll
    for (int i = 0; i < 8; i++) {
        kb4[i] = *(const float4*)(Kz + (long)(lrow + i * 16) * DD + lc4);
        vb4[i] = *(const float4*)(Vz + (long)(lrow + i * 16) * DD + lc4);
    }
    __syncthreads();   // invr + Qs visible

    float iA[4], iB[4];
#pragma unroll
    for (int mf = 0; mf < 4; mf++) {
        iA[mf] = invr[wm + mf * 16 + g];
        iB[mf] = invr[wm + mf * 16 + g + 8];
    }

    float xacc[2][4][4];
#pragma unroll
    for (int i = 0; i < 2; i++)
#pragma unroll
        for (int j = 0; j < 4; j++)
#pragma unroll
            for (int r = 0; r < 4; r++) xacc[i][j][r] = 0.0f;

    for (int kt = 0; kt < 16; kt++) {
#pragma unroll
        for (int i = 0; i < 8; i++) {
            int row = lrow + i * 16;
            uint4 tk = { f2tf32(kb4[i].x), f2tf32(kb4[i].y), f2tf32(kb4[i].z), f2tf32(kb4[i].w) };
            *(uint4*)(&Ks[row * QS + lc4]) = tk;
            uint4 tv = { f2tf32(vb4[i].x), f2tf32(vb4[i].y), f2tf32(vb4[i].z), f2tf32(vb4[i].w) };
            *(uint4*)(&Vs[row * VS + lc4]) = tv;
        }
        __syncthreads();
        if (kt < 15) {
#pragma unroll
            for (int i = 0; i < 8; i++) {
                long off = (long)((kt + 1) * 128 + lrow + i * 16) * DD + lc4;
                kb4[i] = *(const float4*)(Kz + off);
                vb4[i] = *(const float4*)(Vz + off);
            }
        }

        // S = Q K^T (raw)
        float acc[4][4][4];
#pragma unroll
        for (int i = 0; i < 4; i++)
#pragma unroll
            for (int j = 0; j < 4; j++)
#pragma unroll
                for (int r = 0; r < 4; r++) acc[i][j][r] = 0.0f;

#pragma unroll
        for (int ks = 0; ks < 8; ks++) {
            int kb = ks * 8;
            unsigned a[4][4], bf[4][2];
#pragma unroll
            for (int mf = 0; mf < 4; mf++) {
                int m = wm + mf * 16;
                a[mf][0] = Qs[(m + g) * QS + kb + tg];
                a[mf][1] = Qs[(m + g + 8) * QS + kb + tg];
                a[mf][2] = Qs[(m + g) * QS + kb + tg + 4];
                a[mf][3] = Qs[(m + g + 8) * QS + kb + tg + 4];
            }
#pragma unroll
            for (int nf = 0; nf < 4; nf++) {
                int n = wn + nf * 8;
                bf[nf][0] = Ks[(n + g) * QS + kb + tg];
                bf[nf][1] = Ks[(n + g) * QS + kb + tg + 4];
            }
#pragma unroll
            for (int mf = 0; mf < 4; mf++)
#pragma unroll
                for (int nf = 0; nf < 4; nf++)
                    mma_tf32(acc[mf][nf], a[mf], bf[nf]);
        }

        // p = exp(S/8) * inv ; write normalized attn; stage Ps for PV
#pragma unroll
        for (int mf = 0; mf < 4; mf++) {
#pragma unroll
            for (int nf = 0; nf < 4; nf++) {
                int m0 = wm + mf * 16 + g;
                int n0 = wn + nf * 8 + 2 * tg;
                float e0 = ex2f(acc[mf][nf][0] * C1F) * iA[mf];
                float e1 = ex2f(acc[mf][nf][1] * C1F) * iA[mf];
                float e2 = ex2f(acc[mf][nf][2] * C1F) * iB[mf];
                float e3 = ex2f(acc[mf][nf][3] * C1F) * iB[mf];
                *(float2*)(Az + (long)m0 * TT + kt * 128 + n0)       = make_float2(e0, e1);
                *(float2*)(Az + (long)(m0 + 8) * TT + kt * 128 + n0) = make_float2(e2, e3);
                uint2 u0 = { f2tf32(e0), f2tf32(e1) };
                uint2 u1 = { f2tf32(e2), f2tf32(e3) };
                *(uint2*)(&Ps[m0 * PS + n0])       = u0;
                *(uint2*)(&Ps[(m0 + 8) * PS + n0]) = u1;
            }
        }
        __syncthreads();

        // X += P @ V  (PV warp layout)
#pragma unroll
        for (int ks = 0; ks < 16; ks++) {
            int kb = ks * 8;
            unsigned a2[2][4], b2[4][2];
#pragma unroll
            for (int mf = 0; mf < 2; mf++) {
                int m = wm2 + mf * 16;
                a2[mf][0] = Ps[(m + g) * PS + kb + tg];
                a2[mf][1] = Ps[(m + g + 8) * PS + kb + tg];
                a2[mf][2] = Ps[(m + g) * PS + kb + tg + 4];
                a2[mf][3] = Ps[(m + g + 8) * PS + kb + tg + 4];
            }
#pragma unroll
            for (int nf = 0; nf < 4; nf++) {
                int n = wn2 + nf * 8;
                b2[nf][0] = Vs[(kb + tg) * VS + n + g];
                b2[nf][1] = Vs[(kb + tg + 4) * VS + n + g];
            }
#pragma unroll
            for (int mf = 0; mf < 2; mf++)
#pragma unroll
                for (int nf = 0; nf < 4; nf++)
                    mma_tf32(xacc[mf][nf], a2[mf], b2[nf]);
        }
        __syncthreads();
    }

    // X epilogue (already normalized)
#pragma unroll
    for (int mf = 0; mf < 2; mf++)
#pragma unroll
        for (int nf = 0; nf < 4; nf++) {
            int m0 = wm2 + mf * 16 + g;
            int n0 = wn2 + nf * 8 + 2 * tg;
            *(float2*)(Xz + (long)m0 * DD + n0) =
                make_float2(xacc[mf][nf][0], xacc[mf][nf][1]);
            *(float2*)(Xz + (long)(m0 + 8) * DD + n0) =
                make_float2(xacc[mf][nf][2], xacc[mf][nf][3]);
        }
}

#define FATTN2_SMEM ((128 * QS * 2 + 128 * VS + 128 * PS) * 4 + 128 * 4)

// =============================================================================
// residual + LayerNorm: y = LN(query + o) * gamma + beta ; one block per row
// =============================================================================
__global__ __launch_bounds__(256)
void resid_ln_k(const float* __restrict__ q, const float* __restrict__ o,
                const float* __restrict__ gamma, const float* __restrict__ beta,
                float* __restrict__ out)
{
    __shared__ float redA[8], redB[8];
    __shared__ float s_mu, s_rstd;

    long row = blockIdx.x;
    const float* qp = q + row * DD;
    const float* op = o + row * DD;
    float* yp = out + row * DD;
    int tid = threadIdx.x;

    float4 a = *(const float4*)(qp + tid * 4);
    float4 b = *(const float4*)(op + tid * 4);
    float4 y = make_float4(a.x + b.x, a.y + b.y, a.z + b.z, a.w + b.w);

    float s  = y.x + y.y + y.z + y.w;
    float s2 = y.x * y.x + y.y * y.y + y.z * y.z + y.w * y.w;
#pragma unroll
    for (int sh = 16; sh > 0; sh >>= 1) {
        s  += __shfl_xor_sync(0xffffffffu, s,  sh);
        s2 += __shfl_xor_sync(0xffffffffu, s2, sh);
    }
    if ((tid & 31) == 0) { redA[tid >> 5] = s; redB[tid >> 5] = s2; }
    __syncthreads();
    if (tid < 32) {
        float t  = redA[tid & 7];
        float t2 = redB[tid & 7];
#pragma unroll
        for (int sh = 4; sh > 0; sh >>= 1) {
            t  += __shfl_xor_sync(0xffffffffu, t,  sh);
            t2 += __shfl_xor_sync(0xffffffffu, t2, sh);
        }
        if (tid == 0) {
            float mu  = t / (float)DD;
            float var = t2 / (float)DD - mu * mu;
            s_mu = mu;
            s_rstd = rsqrtf(var + 1e-5f);
        }
    }
    __syncthreads();
    float mu = s_mu, rstd = s_rstd;

    float4 gm = *(const float4*)(gamma + tid * 4);
    float4 be = *(const float4*)(beta + tid * 4);
    float4 r;
    r.x = (y.x - mu) * rstd * gm.x + be.x;
    r.y = (y.y - mu) * rstd * gm.y + be.y;
    r.z = (y.z - mu) * rstd * gm.z + be.z;
    r.w = (y.w - mu) * rstd * gm.w + be.w;
    *(float4*)(yp + tid * 4) = r;
}

// =============================================================================
extern "C" void kernel_launch(void* const* d_in, const int* in_sizes, int n_in,
                              void* d_out, int out_size)
{
    const float* query = (const float*)d_in[0];
    const float* key   = (const float*)d_in[1];
    const float* value = (const float*)d_in[2];
    const float* Wq = (const float*)d_in[3];
    const float* bq = (const float*)d_in[4];
    const float* Wk = (const float*)d_in[5];
    const float* bk = (const float*)d_in[6];
    const float* Wv = (const float*)d_in[7];
    const float* bv = (const float*)d_in[8];
    const float* Wo = (const float*)d_in[9];
    const float* bo = (const float*)d_in[10];
    const float* gamma = (const float*)d_in[11];
    const float* beta  = (const float*)d_in[12];

    float* out = (float*)d_out;

    float *q, *k, *v, *x, *o, *attn_scr;
    float2* stats;
    cudaGetSymbolAddress((void**)&q, g_q);
    cudaGetSymbolAddress((void**)&k, g_k);
    cudaGetSymbolAddress((void**)&v, g_v);
    cudaGetSymbolAddress((void**)&x, g_x);
    cudaGetSymbolAddress((void**)&o, g_o);
    cudaGetSymbolAddress((void**)&stats, g_stats);
    cudaGetSymbolAddress((void**)&attn_scr, g_attn_scratch);

    const long y_elems    = (long)BB * TT * DD;
    const long attn_elems = (long)BB * HH * TT * TT;
    float* y_out = out;
    float* attn  = ((long)out_size >= y_elems + attn_elems) ? (out + y_elems)
                                                            : attn_scr;

    static int smem_set = 0;
    if (!smem_set) {
        cudaFuncSetAttribute(mma_nt, cudaFuncAttributeMaxDynamicSharedMemorySize,
                             MMA_NT_SMEM);
        cudaFuncSetAttribute(fstats, cudaFuncAttributeMaxDynamicSharedMemorySize,
                             FSTATS_SMEM);
        cudaFuncSetAttribute(fattn2, cudaFuncAttributeMaxDynamicSharedMemorySize,
                             FATTN2_SMEM);
        smem_set = 1;
    }

    dim3 tpb(256);

    // QKV projections (cp.async pipelined GEMM)
    dim3 gproj(DD / 128, BT / 128, 1);
    mma_nt<<<gproj, tpb, MMA_NT_SMEM>>>(query, DD, Wq, DD, q, DD, bq, DD, 1.0f);
    mma_nt<<<gproj, tpb, MMA_NT_SMEM>>>(key,   DD, Wk, DD, k, DD, bk, DD, 1.0f);
    mma_nt<<<gproj, tpb, MMA_NT_SMEM>>>(value, DD, Wv, DD, v, DD, bv, DD, 1.0f);

    // pass 1: row stats (2 CTAs/SM)
    dim3 gf(1, TT / 128, BB * HH);
    fstats<<<gf, tpb, FSTATS_SMEM>>>(q, k, stats);

    // pass 2: normalized attn write + PV (round-8 structure)
    fattn2<<<gf, tpb, FATTN2_SMEM>>>(q, k, v, stats, attn, x);

    // output projection
    mma_nt<<<gproj, tpb, MMA_NT_SMEM>>>(x, DD, Wo, DD, o, DD, bo, DD, 1.0f);

    // residual + LayerNorm -> y
    resid_ln_k<<<BT, tpb>>>(query, o, gamma, beta, y_out);
}

// round 13
// speedup vs baseline: 1.0768x; 1.0768x over previous
#include <cuda_runtime.h>
#include <cstdint>

#define BB 2
#define TT 2048
#define DD 1024
#define HH 16
#define DKK 64
#define BT 4096   // BB*TT

// ---------------- scratch (device globals; no runtime allocation) -------------
__device__ float g_q[(size_t)BT * DD];
__device__ float g_k[(size_t)BT * DD];
__device__ float g_v[(size_t)BT * DD];
__device__ float g_x[(size_t)BT * DD];
__device__ float g_o[(size_t)BT * DD];
__device__ float2 g_stats[(size_t)BB * HH * TT];   // per (z,row): {raw max, sum exp}
// fallback attn scratch in case d_out only holds y (tuple handling safety)
__device__ float g_attn_scratch[(size_t)BB * HH * TT * TT];

// ----------------------------- helpers ---------------------------------------
__device__ __forceinline__ unsigned f2tf32(float x) {
    unsigned u;
    asm("cvt.rna.tf32.f32 %0, %1;" : "=r"(u) : "f"(x));
    return u;
}

__device__ __forceinline__ float ex2f(float x) {
    float r;
    asm("ex2.approx.ftz.f32 %0, %1;" : "=f"(r) : "f"(x));
    return r;
}

__device__ __forceinline__ void mma_tf32(float c[4], const unsigned a[4], const unsigned b[2]) {
    asm volatile(
        "mma.sync.aligned.m16n8k8.row.col.f32.tf32.tf32.f32 "
        "{%0,%1,%2,%3}, {%4,%5,%6,%7}, {%8,%9}, {%0,%1,%2,%3};"
        : "+f"(c[0]), "+f"(c[1]), "+f"(c[2]), "+f"(c[3])
        : "r"(a[0]), "r"(a[1]), "r"(a[2]), "r"(a[3]), "r"(b[0]), "r"(b[1]));
}

// =============================================================================
// NT tf32 tensor-core GEMM body (r8-proven): 128x128 tile, BK=16, 256 threads,
// register-prefetch pipeline. lda=ldb=ldc=DD, K=DD.
// =============================================================================
#define SK16 20

__device__ __forceinline__
void gemm_body(const float* __restrict__ A, const float* __restrict__ Bm,
               float* __restrict__ C, const float* __restrict__ bias,
               unsigned* As, unsigned* Bs)
{
    int tid = threadIdx.x;
    int lane = tid & 31, wid = tid >> 5;
    int g = lane >> 2, tg = lane & 3;
    int wm = (wid & 1) * 64;
    int wn = (wid >> 1) * 32;

    int bm = blockIdx.y * 128;
    int bn = blockIdx.x * 128;

    int lrow = tid >> 2;          // 0..63
    int lc4  = (tid & 3) * 4;

    const float* Ar0 = A  + (long)(bm + lrow) * DD + lc4;
    const float* Ar1 = A  + (long)(bm + lrow + 64) * DD + lc4;
    const float* Br0 = Bm + (long)(bn + lrow) * DD + lc4;
    const float* Br1 = Bm + (long)(bn + lrow + 64) * DD + lc4;

    float acc[4][4][4];
#pragma unroll
    for (int i = 0; i < 4; i++)
#pragma unroll
        for (int j = 0; j < 4; j++)
#pragma unroll
            for (int r = 0; r < 4; r++) acc[i][j][r] = 0.0f;

    float4 pa0 = *(const float4*)(Ar0);
    float4 pa1 = *(const float4*)(Ar1);
    float4 pb0 = *(const float4*)(Br0);
    float4 pb1 = *(const float4*)(Br1);

    for (int k0 = 0; k0 < DD; k0 += 16) {
        unsigned* da0 = &As[lrow * SK16 + lc4];
        da0[0] = f2tf32(pa0.x); da0[1] = f2tf32(pa0.y);
        da0[2] = f2tf32(pa0.z); da0[3] = f2tf32(pa0.w);
        unsigned* da1 = &As[(lrow + 64) * SK16 + lc4];
        da1[0] = f2tf32(pa1.x); da1[1] = f2tf32(pa1.y);
        da1[2] = f2tf32(pa1.z); da1[3] = f2tf32(pa1.w);
        unsigned* db0 = &Bs[lrow * SK16 + lc4];
        db0[0] = f2tf32(pb0.x); db0[1] = f2tf32(pb0.y);
        db0[2] = f2tf32(pb0.z); db0[3] = f2tf32(pb0.w);
        unsigned* db1 = &Bs[(lrow + 64) * SK16 + lc4];
        db1[0] = f2tf32(pb1.x); db1[1] = f2tf32(pb1.y);
        db1[2] = f2tf32(pb1.z); db1[3] = f2tf32(pb1.w);
        __syncthreads();

        if (k0 + 16 < DD) {
            pa0 = *(const float4*)(Ar0 + k0 + 16);
            pa1 = *(const float4*)(Ar1 + k0 + 16);
            pb0 = *(const float4*)(Br0 + k0 + 16);
            pb1 = *(const float4*)(Br1 + k0 + 16);
        }

#pragma unroll
        for (int ks = 0; ks < 2; ks++) {
            int kb = ks * 8;
            unsigned a[4][4], b[4][2];
#pragma unroll
            for (int mf = 0; mf < 4; mf++) {
                int m = wm + mf * 16;
                a[mf][0] = As[(m + g) * SK16 + kb + tg];
                a[mf][1] = As[(m + g + 8) * SK16 + kb + tg];
                a[mf][2] = As[(m + g) * SK16 + kb + tg + 4];
                a[mf][3] = As[(m + g + 8) * SK16 + kb + tg + 4];
            }
#pragma unroll
            for (int nf = 0; nf < 4; nf++) {
                int n = wn + nf * 8;
                b[nf][0] = Bs[(n + g) * SK16 + kb + tg];
                b[nf][1] = Bs[(n + g) * SK16 + kb + tg + 4];
            }
#pragma unroll
            for (int mf = 0; mf < 4; mf++)
#pragma unroll
                for (int nf = 0; nf < 4; nf++)
                    mma_tf32(acc[mf][nf], a[mf], b[nf]);
        }
        __syncthreads();
    }

#pragma unroll
    for (int mf = 0; mf < 4; mf++) {
#pragma unroll
        for (int nf = 0; nf < 4; nf++) {
            int m0 = bm + wm + mf * 16 + g;
            int n0 = bn + wn + nf * 8 + 2 * tg;
            float b0 = bias[n0];
            float b1 = bias[n0 + 1];
            float* c0 = C + (long)m0 * DD + n0;
            float* c1 = C + (long)(m0 + 8) * DD + n0;
            c0[0] = acc[mf][nf][0] + b0;
            c0[1] = acc[mf][nf][1] + b1;
            c1[0] = acc[mf][nf][2] + b0;
            c1[1] = acc[mf][nf][3] + b1;
        }
    }
}

// fused Q/K/V projections: one launch, blockIdx.z selects the problem
__global__ __launch_bounds__(256, 2)
void proj_qkv(const float* __restrict__ query, const float* __restrict__ key,
              const float* __restrict__ value,
              const float* __restrict__ Wq, const float* __restrict__ Wk,
              const float* __restrict__ Wv,
              const float* __restrict__ bq, const float* __restrict__ bk,
              const float* __restrict__ bv,
              float* __restrict__ qo, float* __restrict__ ko,
              float* __restrict__ vo)
{
    __shared__ unsigned As[128 * SK16];
    __shared__ unsigned Bs[128 * SK16];
    const float *A, *W, *bi;
    float* C;
    if (blockIdx.z == 0)      { A = query; W = Wq; bi = bq; C = qo; }
    else if (blockIdx.z == 1) { A = key;   W = Wk; bi = bk; C = ko; }
    else                      { A = value; W = Wv; bi = bv; C = vo; }
    gemm_body(A, W, C, bi, As, Bs);
}

// output projection
__global__ __launch_bounds__(256, 2)
void proj_o(const float* __restrict__ x, const float* __restrict__ Wo,
            const float* __restrict__ bo, float* __restrict__ o)
{
    __shared__ unsigned As[128 * SK16];
    __shared__ unsigned Bs[128 * SK16];
    gemm_body(x, Wo, o, bo, As, Bs);
}

#define QS 68    // Qs/Ks stride (u32)
#define VS 72    // Vs stride
#define PS 132   // Ps stride
#define C1F 0.18033688f   // 0.125 * log2(e)

// =============================================================================
// Pass 1: row stats (identical to round-8 version). 2 CTAs/SM.
// =============================================================================
__global__ __launch_bounds__(256, 2)
void fstats(const float* __restrict__ Qg, const float* __restrict__ Kg,
            float2* __restrict__ stats)
{
    extern __shared__ unsigned sm1[];
    unsigned* Qs = sm1;                         // [128][QS]
    unsigned* Ks = Qs + 128 * QS;               // [128][QS]
    float* rmax = (float*)(Ks + 128 * QS);      // [4][128]
    float* rsum = rmax + 4 * 128;               // [4][128]

    int z = blockIdx.z, b = z >> 4, h = z & 15;
    int bm = blockIdx.y * 128;
    const float* Qz = Qg + ((long)b * TT + bm) * DD + h * DKK;
    const float* Kz = Kg + (long)b * TT * DD + h * DKK;

    int tid = threadIdx.x, lane = tid & 31, wid = tid >> 5;
    int g = lane >> 2, tg = lane & 3;
    int wm = (wid & 1) * 64, wn = (wid >> 1) * 32;
    int wnidx = wid >> 1;

    int lrow = tid >> 4;           // 0..15
    int lc4  = (tid & 15) * 4;     // 0..60

#pragma unroll
    for (int i = 0; i < 8; i++) {
        int row = lrow + i * 16;
        float4 qv = *(const float4*)(Qz + (long)row * DD + lc4);
        uint4 t = { f2tf32(qv.x), f2tf32(qv.y), f2tf32(qv.z), f2tf32(qv.w) };
        *(uint4*)(&Qs[row * QS + lc4]) = t;
    }

    float Mloc[4][2], Tloc[4][2];
#pragma unroll
    for (int mf = 0; mf < 4; mf++) {
        Mloc[mf][0] = Mloc[mf][1] = -1e30f;
        Tloc[mf][0] = Tloc[mf][1] = 0.0f;
    }

    for (int kt = 0; kt < 16; kt++) {
        __syncthreads();
#pragma unroll
        for (int i = 0; i < 8; i++) {
            int row = lrow + i * 16;
            float4 kv = *(const float4*)(Kz + (long)(kt * 128 + row) * DD + lc4);
            uint4 t = { f2tf32(kv.x), f2tf32(kv.y), f2tf32(kv.z), f2tf32(kv.w) };
            *(uint4*)(&Ks[row * QS + lc4]) = t;
        }
        __syncthreads();

        float acc[4][4][4];
#pragma unroll
        for (int i = 0; i < 4; i++)
#pragma unroll
            for (int j = 0; j < 4; j++)
#pragma unroll
                for (int r = 0; r < 4; r++) acc[i][j][r] = 0.0f;

#pragma unroll
        for (int ks = 0; ks < 8; ks++) {
            int kb = ks * 8;
            unsigned a[4][4], bf[4][2];
#pragma unroll
            for (int mf = 0; mf < 4; mf++) {
                int m = wm + mf * 16;
                a[mf][0] = Qs[(m + g) * QS + kb + tg];
                a[mf][1] = Qs[(m + g + 8) * QS + kb + tg];
                a[mf][2] = Qs[(m + g) * QS + kb + tg + 4];
                a[mf][3] = Qs[(m + g + 8) * QS + kb + tg + 4];
            }
#pragma unroll
            for (int nf = 0; nf < 4; nf++) {
                int n = wn + nf * 8;
                bf[nf][0] = Ks[(n + g) * QS + kb + tg];
                bf[nf][1] = Ks[(n + g) * QS + kb + tg + 4];
            }
#pragma unroll
            for (int mf = 0; mf < 4; mf++)
#pragma unroll
                for (int nf = 0; nf < 4; nf++)
                    mma_tf32(acc[mf][nf], a[mf], bf[nf]);
        }

#pragma unroll
        for (int mf = 0; mf < 4; mf++) {
#pragma unroll
            for (int nf = 0; nf < 4; nf++) {
                Mloc[mf][0] = fmaxf(Mloc[mf][0], fmaxf(acc[mf][nf][0], acc[mf][nf][1]));
                Mloc[mf][1] = fmaxf(Mloc[mf][1], fmaxf(acc[mf][nf][2], acc[mf][nf][3]));
                Tloc[mf][0] += ex2f(acc[mf][nf][0] * C1F) + ex2f(acc[mf][nf][1] * C1F);
                Tloc[mf][1] += ex2f(acc[mf][nf][2] * C1F) + ex2f(acc[mf][nf][3] * C1F);
            }
        }
    }

#pragma unroll
    for (int mf = 0; mf < 4; mf++)
#pragma unroll
        for (int i = 0; i < 2; i++) {
            float m = Mloc[mf][i], t = Tloc[mf][i];
#pragma unroll
            for (int sft = 1; sft <= 2; sft <<= 1) {
                m = fmaxf(m, __shfl_xor_sync(0xffffffffu, m, sft));
                t += __shfl_xor_sync(0xffffffffu, t, sft);
            }
            if (tg == 0) {
                int row = wm + mf * 16 + g + i * 8;
                rmax[wnidx * 128 + row] = m;
                rsum[wnidx * 128 + row] = t;
            }
        }
    __syncthreads();
    if (tid < 128) {
        float M = fmaxf(fmaxf(rmax[tid], rmax[128 + tid]),
                        fmaxf(rmax[256 + tid], rmax[384 + tid]));
        float T = rsum[tid] + rsum[128 + tid] + rsum[256 + tid] + rsum[384 + tid];
        stats[(long)z * TT + bm + tid] = make_float2(M, T);
    }
}

#define FSTATS_SMEM ((128 * QS * 2) * 4 + (4 * 128 * 2) * 4)

// =============================================================================
// Pass 2: recompute S, write NORMALIZED attn once, PV -> X.
// (identical to round-8 version — best measured)
// =============================================================================
__global__ __launch_bounds__(256, 1)
void fattn2(const float* __restrict__ Qg, const float* __restrict__ Kg,
            const float* __restrict__ Vg, const float2* __restrict__ stats,
            float* __restrict__ attn, float* __restrict__ Xg)
{
    extern __shared__ unsigned smem_u[];
    unsigned* Qs = smem_u;                          // [128][QS]
    unsigned* Ks = Qs + 128 * QS;                   // [128][QS]
    unsigned* Vs = Ks + 128 * QS;                   // [128][VS]
    unsigned* Ps = Vs + 128 * VS;                   // [128][PS]
    float* invr = (float*)(Ps + 128 * PS);          // [128]

    int z = blockIdx.z, b = z >> 4, h = z & 15;
    int bm = blockIdx.y * 128;
    const float* Qz = Qg + ((long)b * TT + bm) * DD + h * DKK;
    const float* Kz = Kg + (long)b * TT * DD + h * DKK;
    const float* Vz = Vg + (long)b * TT * DD + h * DKK;
    float* Az = attn + (long)z * TT * TT + (long)bm * TT;
    float* Xz = Xg + ((long)b * TT + bm) * DD + h * DKK;

    int tid = threadIdx.x, lane = tid & 31, wid = tid >> 5;
    int g = lane >> 2, tg = lane & 3;
    int wm = (wid & 1) * 64, wn = (wid >> 1) * 32;      // QK warp layout (2m x 4n)
    int wm2 = (wid >> 1) * 32, wn2 = (wid & 1) * 32;    // PV warp layout (4m x 2n)

    int lrow = tid >> 4;           // 0..15
    int lc4  = (tid & 15) * 4;     // 0..60

    // inv per row from stats
    if (tid < 128) {
        float2 st = stats[(long)z * TT + bm + tid];
        invr[tid] = 1.0f / (ex2f(st.x * C1F) + st.y);   // softmax-one denominator
    }

    // load Q tile -> Qs tf32
#pragma unroll
    for (int i = 0; i < 8; i++) {
        int row = lrow + i * 16;
        float4 qv = *(const float4*)(Qz + (long)row * DD + lc4);
        uint4 t = { f2tf32(qv.x), f2tf32(qv.y), f2tf32(qv.z), f2tf32(qv.w) };
        *(uint4*)(&Qs[row * QS + lc4]) = t;
    }

    // K/V register prefetch of tile 0
    float4 kb4[8], vb4[8];
#pragma unroll
    for (int i = 0; i < 8; i++) {
        kb4[i] = *(const float4*)(Kz + (long)(lrow + i * 16) * DD + lc4);
        vb4[i] = *(const float4*)(Vz + (long)(lrow + i * 16) * DD + lc4);
    }
    __syncthreads();   // invr + Qs visible

    float iA[4], iB[4];
#pragma unroll
    for (int mf = 0; mf < 4; mf++) {
        iA[mf] = invr[wm + mf * 16 + g];
        iB[mf] = invr[wm + mf * 16 + g + 8];
    }

    float xacc[2][4][4];
#pragma unroll
    for (int i = 0; i < 2; i++)
#pragma unroll
        for (int j = 0; j < 4; j++)
#pragma unroll
            for (int r = 0; r < 4; r++) xacc[i][j][r] = 0.0f;

    for (int kt = 0; kt < 16; kt++) {
#pragma unroll
        for (int i = 0; i < 8; i++) {
            int row = lrow + i * 16;
            uint4 tk = { f2tf32(kb4[i].x), f2tf32(kb4[i].y), f2tf32(kb4[i].z), f2tf32(kb4[i].w) };
            *(uint4*)(&Ks[row * QS + lc4]) = tk;
            uint4 tv = { f2tf32(vb4[i].x), f2tf32(vb4[i].y), f2tf32(vb4[i].z), f2tf32(vb4[i].w) };
            *(uint4*)(&Vs[row * VS + lc4]) = tv;
        }
        __syncthreads();
        if (kt < 15) {
#pragma unroll
            for (int i = 0; i < 8; i++) {
                long off = (long)((kt + 1) * 128 + lrow + i * 16) * DD + lc4;
                kb4[i] = *(const float4*)(Kz + off);
                vb4[i] = *(const float4*)(Vz + off);
            }
        }

        // S = Q K^T (raw)
        float acc[4][4][4];
#pragma unroll
        for (int i = 0; i < 4; i++)
#pragma unroll
            for (int j = 0; j < 4; j++)
#pragma unroll
                for (int r = 0; r < 4; r++) acc[i][j][r] = 0.0f;

#pragma unroll
        for (int ks = 0; ks < 8; ks++) {
            int kb = ks * 8;
            unsigned a[4][4], bf[4][2];
#pragma unroll
            for (int mf = 0; mf < 4; mf++) {
                int m = wm + mf * 16;
                a[mf][0] = Qs[(m + g) * QS + kb + tg];
                a[mf][1] = Qs[(m + g + 8) * QS + kb + tg];
                a[mf][2] = Qs[(m + g) * QS + kb + tg + 4];
                a[mf][3] = Qs[(m + g + 8) * QS + kb + tg + 4];
            }
#pragma unroll
            for (int nf = 0; nf < 4; nf++) {
                int n = wn + nf * 8;
                bf[nf][0] = Ks[(n + g) * QS + kb + tg];
                bf[nf][1] = Ks[(n + g) * QS + kb + tg + 4];
            }
#pragma unroll
            for (int mf = 0; mf < 4; mf++)
#pragma unroll
                for (int nf = 0; nf < 4; nf++)
                    mma_tf32(acc[mf][nf], a[mf], bf[nf]);
        }

        // p = exp(S/8) * inv ; write normalized attn; stage Ps for PV
#pragma unroll
        for (int mf = 0; mf < 4; mf++) {
#pragma unroll
            for (int nf = 0; nf < 4; nf++) {
                int m0 = wm + mf * 16 + g;
                int n0 = wn + nf * 8 + 2 * tg;
                float e0 = ex2f(acc[mf][nf][0] * C1F) * iA[mf];
                float e1 = ex2f(acc[mf][nf][1] * C1F) * iA[mf];
                float e2 = ex2f(acc[mf][nf][2] * C1F) * iB[mf];
                float e3 = ex2f(acc[mf][nf][3] * C1F) * iB[mf];
                *(float2*)(Az + (long)m0 * TT + kt * 128 + n0)       = make_float2(e0, e1);
                *(float2*)(Az + (long)(m0 + 8) * TT + kt * 128 + n0) = make_float2(e2, e3);
                uint2 u0 = { f2tf32(e0), f2tf32(e1) };
                uint2 u1 = { f2tf32(e2), f2tf32(e3) };
                *(uint2*)(&Ps[m0 * PS + n0])       = u0;
                *(uint2*)(&Ps[(m0 + 8) * PS + n0]) = u1;
            }
        }
        __syncthreads();

        // X += P @ V  (PV warp layout)
#pragma unroll
        for (int ks = 0; ks < 16; ks++) {
            int kb = ks * 8;
            unsigned a2[2][4], b2[4][2];
#pragma unroll
            for (int mf = 0; mf < 2; mf++) {
                int m = wm2 + mf * 16;
                a2[mf][0] = Ps[(m + g) * PS + kb + tg];
                a2[mf][1] = Ps[(m + g + 8) * PS + kb + tg];
                a2[mf][2] = Ps[(m + g) * PS + kb + tg + 4];
                a2[mf][3] = Ps[(m + g + 8) * PS + kb + tg + 4];
            }
#pragma unroll
            for (int nf = 0; nf < 4; nf++) {
                int n = wn2 + nf * 8;
                b2[nf][0] = Vs[(kb + tg) * VS + n + g];
                b2[nf][1] = Vs[(kb + tg + 4) * VS + n + g];
            }
#pragma unroll
            for (int mf = 0; mf < 2; mf++)
#pragma unroll
                for (int nf = 0; nf < 4; nf++)
                    mma_tf32(xacc[mf][nf], a2[mf], b2[nf]);
        }
        __syncthreads();
    }

    // X epilogue (already normalized)
#pragma unroll
    for (int mf = 0; mf < 2; mf++)
#pragma unroll
        for (int nf = 0; nf < 4; nf++) {
            int m0 = wm2 + mf * 16 + g;
            int n0 = wn2 + nf * 8 + 2 * tg;
            *(float2*)(Xz + (long)m0 * DD + n0) =
                make_float2(xacc[mf][nf][0], xacc[mf][nf][1]);
            *(float2*)(Xz + (long)(m0 + 8) * DD + n0) =
                make_float2(xacc[mf][nf][2], xacc[mf][nf][3]);
        }
}

#define FATTN2_SMEM ((128 * QS * 2 + 128 * VS + 128 * PS) * 4 + 128 * 4)

// =============================================================================
// residual + LayerNorm: y = LN(query + o) * gamma + beta ; one block per row
// =============================================================================
__global__ __launch_bounds__(256)
void resid_ln_k(const float* __restrict__ q, const float* __restrict__ o,
                const float* __restrict__ gamma, const float* __restrict__ beta,
                float* __restrict__ out)
{
    __shared__ float redA[8], redB[8];
    __shared__ float s_mu, s_rstd;

    long row = blockIdx.x;
    const float* qp = q + row * DD;
    const float* op = o + row * DD;
    float* yp = out + row * DD;
    int tid = threadIdx.x;

    float4 a = *(const float4*)(qp + tid * 4);
    float4 b = *(const float4*)(op + tid * 4);
    float4 y = make_float4(a.x + b.x, a.y + b.y, a.z + b.z, a.w + b.w);

    float s  = y.x + y.y + y.z + y.w;
    float s2 = y.x * y.x + y.y * y.y + y.z * y.z + y.w * y.w;
#pragma unroll
    for (int sh = 16; sh > 0; sh >>= 1) {
        s  += __shfl_xor_sync(0xffffffffu, s,  sh);
        s2 += __shfl_xor_sync(0xffffffffu, s2, sh);
    }
    if ((tid & 31) == 0) { redA[tid >> 5] = s; redB[tid >> 5] = s2; }
    __syncthreads();
    if (tid < 32) {
        float t  = redA[tid & 7];
        float t2 = redB[tid & 7];
#pragma unroll
        for (int sh = 4; sh > 0; sh >>= 1) {
            t  += __shfl_xor_sync(0xffffffffu, t,  sh);
            t2 += __shfl_xor_sync(0xffffffffu, t2, sh);
        }
        if (tid == 0) {
            float mu  = t / (float)DD;
            float var = t2 / (float)DD - mu * mu;
            s_mu = mu;
            s_rstd = rsqrtf(var + 1e-5f);
        }
    }
    __syncthreads();
    float mu = s_mu, rstd = s_rstd;

    float4 gm = *(const float4*)(gamma + tid * 4);
    float4 be = *(const float4*)(beta + tid * 4);
    float4 r;
    r.x = (y.x - mu) * rstd * gm.x + be.x;
    r.y = (y.y - mu) * rstd * gm.y + be.y;
    r.z = (y.z - mu) * rstd * gm.z + be.z;
    r.w = (y.w - mu) * rstd * gm.w + be.w;
    *(float4*)(yp + tid * 4) = r;
}

// =============================================================================
extern "C" void kernel_launch(void* const* d_in, const int* in_sizes, int n_in,
                              void* d_out, int out_size)
{
    const float* query = (const float*)d_in[0];
    const float* key   = (const float*)d_in[1];
    const float* value = (const float*)d_in[2];
    const float* Wq = (const float*)d_in[3];
    const float* bq = (const float*)d_in[4];
    const float* Wk = (const float*)d_in[5];
    const float* bk = (const float*)d_in[6];
    const float* Wv = (const float*)d_in[7];
    const float* bv = (const float*)d_in[8];
    const float* Wo = (const float*)d_in[9];
    const float* bo = (const float*)d_in[10];
    const float* gamma = (const float*)d_in[11];
    const float* beta  = (const float*)d_in[12];

    float* out = (float*)d_out;

    float *q, *k, *v, *x, *o, *attn_scr;
    float2* stats;
    cudaGetSymbolAddress((void**)&q, g_q);
    cudaGetSymbolAddress((void**)&k, g_k);
    cudaGetSymbolAddress((void**)&v, g_v);
    cudaGetSymbolAddress((void**)&x, g_x);
    cudaGetSymbolAddress((void**)&o, g_o);
    cudaGetSymbolAddress((void**)&stats, g_stats);
    cudaGetSymbolAddress((void**)&attn_scr, g_attn_scratch);

    const long y_elems    = (long)BB * TT * DD;
    const long attn_elems = (long)BB * HH * TT * TT;
    float* y_out = out;
    float* attn  = ((long)out_size >= y_elems + attn_elems) ? (out + y_elems)
                                                            : attn_scr;

    static int smem_set = 0;
    if (!smem_set) {
        cudaFuncSetAttribute(fstats, cudaFuncAttributeMaxDynamicSharedMemorySize,
                             FSTATS_SMEM);
        cudaFuncSetAttribute(fattn2, cudaFuncAttributeMaxDynamicSharedMemorySize,
                             FATTN2_SMEM);
        smem_set = 1;
    }

    dim3 tpb(256);

    // Q/K/V projections: ONE launch, 768 CTAs (better wave packing, no gaps)
    dim3 gqkv(DD / 128, BT / 128, 3);
    proj_qkv<<<gqkv, tpb>>>(query, key, value, Wq, Wk, Wv, bq, bk, bv, q, k, v);

    // pass 1: row stats (2 CTAs/SM)
    dim3 gf(1, TT / 128, BB * HH);
    fstats<<<gf, tpb, FSTATS_SMEM>>>(q, k, stats);

    // pass 2: normalized attn write + PV (round-8 structure)
    fattn2<<<gf, tpb, FATTN2_SMEM>>>(q, k, v, stats, attn, x);

    // output projection
    dim3 gproj(DD / 128, BT / 128, 1);
    proj_o<<<gproj, tpb>>>(x, Wo, bo, o);

    // residual + LayerNorm -> y
    resid_ln_k<<<BT, tpb>>>(query, o, gamma, beta, y_out);
}

// round 14
// speedup vs baseline: 1.1992x; 1.1137x over previous
#include <cuda_runtime.h>
#include <cstdint>

#define BB 2
#define TT 2048
#define DD 1024
#define HH 16
#define DKK 64
#define BT 4096   // BB*TT

// ---------------- scratch (device globals; no runtime allocation) -------------
__device__ float g_q[(size_t)BT * DD];
__device__ float g_k[(size_t)BT * DD];
__device__ float g_v[(size_t)BT * DD];
__device__ float g_x[(size_t)BT * DD];
__device__ float g_o[(size_t)BT * DD];
__device__ float2 g_stats[(size_t)BB * HH * TT];   // per (z,row): {raw max, sum exp}
// fallback attn scratch in case d_out only holds y (tuple handling safety)
__device__ float g_attn_scratch[(size_t)BB * HH * TT * TT];

// ----------------------------- helpers ---------------------------------------
__device__ __forceinline__ unsigned f2tf32(float x) {
    unsigned u;
    asm("cvt.rna.tf32.f32 %0, %1;" : "=r"(u) : "f"(x));
    return u;
}

__device__ __forceinline__ float ex2f(float x) {
    float r;
    asm("ex2.approx.ftz.f32 %0, %1;" : "=f"(r) : "f"(x));
    return r;
}

__device__ __forceinline__ void mma_tf32(float c[4], const unsigned a[4], const unsigned b[2]) {
    asm volatile(
        "mma.sync.aligned.m16n8k8.row.col.f32.tf32.tf32.f32 "
        "{%0,%1,%2,%3}, {%4,%5,%6,%7}, {%8,%9}, {%0,%1,%2,%3};"
        : "+f"(c[0]), "+f"(c[1]), "+f"(c[2]), "+f"(c[3])
        : "r"(a[0]), "r"(a[1]), "r"(a[2]), "r"(a[3]), "r"(b[0]), "r"(b[1]));
}

#define QS 68    // smem row stride (u32) for 128x64 tiles
#define VS 72    // Vs stride
#define PS 132   // Ps stride
#define C1F 0.18033688f   // 0.125 * log2(e)

// =============================================================================
// Projection GEMM body, fstats-structured: BK=64, 16 k-iterations,
// 128 mma per barrier interval (was 32). NT, +bias, all dims DD.
// Same sequential k accumulation order as before -> bit-identical results.
// =============================================================================
__device__ __forceinline__
void gemm_body(const float* __restrict__ A, const float* __restrict__ Bm,
               float* __restrict__ C, const float* __restrict__ bias,
               unsigned* As, unsigned* Bs)
{
    int tid = threadIdx.x;
    int lane = tid & 31, wid = tid >> 5;
    int g = lane >> 2, tg = lane & 3;
    int wm = (wid & 1) * 64;
    int wn = (wid >> 1) * 32;

    int bm = blockIdx.y * 128;
    int bn = blockIdx.x * 128;

    int lrow = tid >> 4;           // 0..15
    int lc4  = (tid & 15) * 4;     // 0..60

    const float* Ag = A  + (long)bm * DD;
    const float* Bg = Bm + (long)bn * DD;

    float acc[4][4][4];
#pragma unroll
    for (int i = 0; i < 4; i++)
#pragma unroll
        for (int j = 0; j < 4; j++)
#pragma unroll
            for (int r = 0; r < 4; r++) acc[i][j][r] = 0.0f;

    for (int kt = 0; kt < 16; kt++) {
        __syncthreads();
        // load A tile (128 x 64) and B tile (128 x 64), cvt tf32, STS
#pragma unroll
        for (int i = 0; i < 8; i++) {
            int row = lrow + i * 16;
            float4 av = *(const float4*)(Ag + (long)row * DD + kt * 64 + lc4);
            uint4 ta = { f2tf32(av.x), f2tf32(av.y), f2tf32(av.z), f2tf32(av.w) };
            *(uint4*)(&As[row * QS + lc4]) = ta;
            float4 bv = *(const float4*)(Bg + (long)row * DD + kt * 64 + lc4);
            uint4 tb = { f2tf32(bv.x), f2tf32(bv.y), f2tf32(bv.z), f2tf32(bv.w) };
            *(uint4*)(&Bs[row * QS + lc4]) = tb;
        }
        __syncthreads();

#pragma unroll
        for (int ks = 0; ks < 8; ks++) {
            int kb = ks * 8;
            unsigned a[4][4], b[4][2];
#pragma unroll
            for (int mf = 0; mf < 4; mf++) {
                int m = wm + mf * 16;
                a[mf][0] = As[(m + g) * QS + kb + tg];
                a[mf][1] = As[(m + g + 8) * QS + kb + tg];
                a[mf][2] = As[(m + g) * QS + kb + tg + 4];
                a[mf][3] = As[(m + g + 8) * QS + kb + tg + 4];
            }
#pragma unroll
            for (int nf = 0; nf < 4; nf++) {
                int n = wn + nf * 8;
                b[nf][0] = Bs[(n + g) * QS + kb + tg];
                b[nf][1] = Bs[(n + g) * QS + kb + tg + 4];
            }
#pragma unroll
            for (int mf = 0; mf < 4; mf++)
#pragma unroll
                for (int nf = 0; nf < 4; nf++)
                    mma_tf32(acc[mf][nf], a[mf], b[nf]);
        }
    }

#pragma unroll
    for (int mf = 0; mf < 4; mf++) {
#pragma unroll
        for (int nf = 0; nf < 4; nf++) {
            int m0 = bm + wm + mf * 16 + g;
            int n0 = bn + wn + nf * 8 + 2 * tg;
            float b0 = bias[n0];
            float b1 = bias[n0 + 1];
            float* c0 = C + (long)m0 * DD + n0;
            float* c1 = C + (long)(m0 + 8) * DD + n0;
            c0[0] = acc[mf][nf][0] + b0;
            c0[1] = acc[mf][nf][1] + b1;
            c1[0] = acc[mf][nf][2] + b0;
            c1[1] = acc[mf][nf][3] + b1;
        }
    }
}

#define FPROJ_SMEM (2 * 128 * QS * 4)

// fused Q/K/V projections: one launch, blockIdx.z selects the problem
__global__ __launch_bounds__(256, 2)
void proj_qkv(const float* __restrict__ query, const float* __restrict__ key,
              const float* __restrict__ value,
              const float* __restrict__ Wq, const float* __restrict__ Wk,
              const float* __restrict__ Wv,
              const float* __restrict__ bq, const float* __restrict__ bk,
              const float* __restrict__ bv,
              float* __restrict__ qo, float* __restrict__ ko,
              float* __restrict__ vo)
{
    extern __shared__ unsigned smp[];
    unsigned* As = smp;
    unsigned* Bs = smp + 128 * QS;
    const float *A, *W, *bi;
    float* C;
    if (blockIdx.z == 0)      { A = query; W = Wq; bi = bq; C = qo; }
    else if (blockIdx.z == 1) { A = key;   W = Wk; bi = bk; C = ko; }
    else                      { A = value; W = Wv; bi = bv; C = vo; }
    gemm_body(A, W, C, bi, As, Bs);
}

// output projection
__global__ __launch_bounds__(256, 2)
void proj_o(const float* __restrict__ x, const float* __restrict__ Wo,
            const float* __restrict__ bo, float* __restrict__ o)
{
    extern __shared__ unsigned smp[];
    unsigned* As = smp;
    unsigned* Bs = smp + 128 * QS;
    gemm_body(x, Wo, o, bo, As, Bs);
}

// =============================================================================
// Pass 1: row stats (identical to round-8 version). 2 CTAs/SM.
// =============================================================================
__global__ __launch_bounds__(256, 2)
void fstats(const float* __restrict__ Qg, const float* __restrict__ Kg,
            float2* __restrict__ stats)
{
    extern __shared__ unsigned sm1[];
    unsigned* Qs = sm1;                         // [128][QS]
    unsigned* Ks = Qs + 128 * QS;               // [128][QS]
    float* rmax = (float*)(Ks + 128 * QS);      // [4][128]
    float* rsum = rmax + 4 * 128;               // [4][128]

    int z = blockIdx.z, b = z >> 4, h = z & 15;
    int bm = blockIdx.y * 128;
    const float* Qz = Qg + ((long)b * TT + bm) * DD + h * DKK;
    const float* Kz = Kg + (long)b * TT * DD + h * DKK;

    int tid = threadIdx.x, lane = tid & 31, wid = tid >> 5;
    int g = lane >> 2, tg = lane & 3;
    int wm = (wid & 1) * 64, wn = (wid >> 1) * 32;
    int wnidx = wid >> 1;

    int lrow = tid >> 4;           // 0..15
    int lc4  = (tid & 15) * 4;     // 0..60

#pragma unroll
    for (int i = 0; i < 8; i++) {
        int row = lrow + i * 16;
        float4 qv = *(const float4*)(Qz + (long)row * DD + lc4);
        uint4 t = { f2tf32(qv.x), f2tf32(qv.y), f2tf32(qv.z), f2tf32(qv.w) };
        *(uint4*)(&Qs[row * QS + lc4]) = t;
    }

    float Mloc[4][2], Tloc[4][2];
#pragma unroll
    for (int mf = 0; mf < 4; mf++) {
        Mloc[mf][0] = Mloc[mf][1] = -1e30f;
        Tloc[mf][0] = Tloc[mf][1] = 0.0f;
    }

    for (int kt = 0; kt < 16; kt++) {
        __syncthreads();
#pragma unroll
        for (int i = 0; i < 8; i++) {
            int row = lrow + i * 16;
            float4 kv = *(const float4*)(Kz + (long)(kt * 128 + row) * DD + lc4);
            uint4 t = { f2tf32(kv.x), f2tf32(kv.y), f2tf32(kv.z), f2tf32(kv.w) };
            *(uint4*)(&Ks[row * QS + lc4]) = t;
        }
        __syncthreads();

        float acc[4][4][4];
#pragma unroll
        for (int i = 0; i < 4; i++)
#pragma unroll
            for (int j = 0; j < 4; j++)
#pragma unroll
                for (int r = 0; r < 4; r++) acc[i][j][r] = 0.0f;

#pragma unroll
        for (int ks = 0; ks < 8; ks++) {
            int kb = ks * 8;
            unsigned a[4][4], bf[4][2];
#pragma unroll
            for (int mf = 0; mf < 4; mf++) {
                int m = wm + mf * 16;
                a[mf][0] = Qs[(m + g) * QS + kb + tg];
                a[mf][1] = Qs[(m + g + 8) * QS + kb + tg];
                a[mf][2] = Qs[(m + g) * QS + kb + tg + 4];
                a[mf][3] = Qs[(m + g + 8) * QS + kb + tg + 4];
            }
#pragma unroll
            for (int nf = 0; nf < 4; nf++) {
                int n = wn + nf * 8;
                bf[nf][0] = Ks[(n + g) * QS + kb + tg];
                bf[nf][1] = Ks[(n + g) * QS + kb + tg + 4];
            }
#pragma unroll
            for (int mf = 0; mf < 4; mf++)
#pragma unroll
                for (int nf = 0; nf < 4; nf++)
                    mma_tf32(acc[mf][nf], a[mf], bf[nf]);
        }

#pragma unroll
        for (int mf = 0; mf < 4; mf++) {
#pragma unroll
            for (int nf = 0; nf < 4; nf++) {
                Mloc[mf][0] = fmaxf(Mloc[mf][0], fmaxf(acc[mf][nf][0], acc[mf][nf][1]));
                Mloc[mf][1] = fmaxf(Mloc[mf][1], fmaxf(acc[mf][nf][2], acc[mf][nf][3]));
                Tloc[mf][0] += ex2f(acc[mf][nf][0] * C1F) + ex2f(acc[mf][nf][1] * C1F);
                Tloc[mf][1] += ex2f(acc[mf][nf][2] * C1F) + ex2f(acc[mf][nf][3] * C1F);
            }
        }
    }

#pragma unroll
    for (int mf = 0; mf < 4; mf++)
#pragma unroll
        for (int i = 0; i < 2; i++) {
            float m = Mloc[mf][i], t = Tloc[mf][i];
#pragma unroll
            for (int sft = 1; sft <= 2; sft <<= 1) {
                m = fmaxf(m, __shfl_xor_sync(0xffffffffu, m, sft));
                t += __shfl_xor_sync(0xffffffffu, t, sft);
            }
            if (tg == 0) {
                int row = wm + mf * 16 + g + i * 8;
                rmax[wnidx * 128 + row] = m;
                rsum[wnidx * 128 + row] = t;
            }
        }
    __syncthreads();
    if (tid < 128) {
        float M = fmaxf(fmaxf(rmax[tid], rmax[128 + tid]),
                        fmaxf(rmax[256 + tid], rmax[384 + tid]));
        float T = rsum[tid] + rsum[128 + tid] + rsum[256 + tid] + rsum[384 + tid];
        stats[(long)z * TT + bm + tid] = make_float2(M, T);
    }
}

#define FSTATS_SMEM ((128 * QS * 2) * 4 + (4 * 128 * 2) * 4)

// =============================================================================
// Pass 2: recompute S, write NORMALIZED attn once, PV -> X.
// (identical to round-8 version — best measured)
// =============================================================================
__global__ __launch_bounds__(256, 1)
void fattn2(const float* __restrict__ Qg, const float* __restrict__ Kg,
            const float* __restrict__ Vg, const float2* __restrict__ stats,
            float* __restrict__ attn, float* __restrict__ Xg)
{
    extern __shared__ unsigned smem_u[];
    unsigned* Qs = smem_u;                          // [128][QS]
    unsigned* Ks = Qs + 128 * QS;                   // [128][QS]
    unsigned* Vs = Ks + 128 * QS;                   // [128][VS]
    unsigned* Ps = Vs + 128 * VS;                   // [128][PS]
    float* invr = (float*)(Ps + 128 * PS);          // [128]

    int z = blockIdx.z, b = z >> 4, h = z & 15;
    int bm = blockIdx.y * 128;
    const float* Qz = Qg + ((long)b * TT + bm) * DD + h * DKK;
    const float* Kz = Kg + (long)b * TT * DD + h * DKK;
    const float* Vz = Vg + (long)b * TT * DD + h * DKK;
    float* Az = attn + (long)z * TT * TT + (long)bm * TT;
    float* Xz = Xg + ((long)b * TT + bm) * DD + h * DKK;

    int tid = threadIdx.x, lane = tid & 31, wid = tid >> 5;
    int g = lane >> 2, tg = lane & 3;
    int wm = (wid & 1) * 64, wn = (wid >> 1) * 32;      // QK warp layout (2m x 4n)
    int wm2 = (wid >> 1) * 32, wn2 = (wid & 1) * 32;    // PV warp layout (4m x 2n)

    int lrow = tid >> 4;           // 0..15
    int lc4  = (tid & 15) * 4;     // 0..60

    // inv per row from stats
    if (tid < 128) {
        float2 st = stats[(long)z * TT + bm + tid];
        invr[tid] = 1.0f / (ex2f(st.x * C1F) + st.y);   // softmax-one denominator
    }

    // load Q tile -> Qs tf32
#pragma unroll
    for (int i = 0; i < 8; i++) {
        int row = lrow + i * 16;
        float4 qv = *(const float4*)(Qz + (long)row * DD + lc4);
        uint4 t = { f2tf32(qv.x), f2tf32(qv.y), f2tf32(qv.z), f2tf32(qv.w) };
        *(uint4*)(&Qs[row * QS + lc4]) = t;
    }

    // K/V register prefetch of tile 0
    float4 kb4[8], vb4[8];
#pragma unroll
    for (int i = 0; i < 8; i++) {
        kb4[i] = *(const float4*)(Kz + (long)(lrow + i * 16) * DD + lc4);
        vb4[i] = *(const float4*)(Vz + (long)(lrow + i * 16) * DD + lc4);
    }
    __syncthreads();   // invr + Qs visible

    float iA[4], iB[4];
#pragma unroll
    for (int mf = 0; mf < 4; mf++) {
        iA[mf] = invr[wm + mf * 16 + g];
        iB[mf] = invr[wm + mf * 16 + g + 8];
    }

    float xacc[2][4][4];
#pragma unroll
    for (int i = 0; i < 2; i++)
#pragma unroll
        for (int j = 0; j < 4; j++)
#pragma unroll
            for (int r = 0; r < 4; r++) xacc[i][j][r] = 0.0f;

    for (int kt = 0; kt < 16; kt++) {
#pragma unroll
        for (int i = 0; i < 8; i++) {
            int row = lrow + i * 16;
            uint4 tk = { f2tf32(kb4[i].x), f2tf32(kb4[i].y), f2tf32(kb4[i].z), f2tf32(kb4[i].w) };
            *(uint4*)(&Ks[row * QS + lc4]) = tk;
            uint4 tv = { f2tf32(vb4[i].x), f2tf32(vb4[i].y), f2tf32(vb4[i].z), f2tf32(vb4[i].w) };
            *(uint4*)(&Vs[row * VS + lc4]) = tv;
        }
        __syncthreads();
        if (kt < 15) {
#pragma unroll
            for (int i = 0; i < 8; i++) {
                long off = (long)((kt + 1) * 128 + lrow + i * 16) * DD + lc4;
                kb4[i] = *(const float4*)(Kz + off);
                vb4[i] = *(const float4*)(Vz + off);
            }
        }

        // S = Q K^T (raw)
        float acc[4][4][4];
#pragma unroll
        for (int i = 0; i < 4; i++)
#pragma unroll
            for (int j = 0; j < 4; j++)
#pragma unroll
                for (int r = 0; r < 4; r++) acc[i][j][r] = 0.0f;

#pragma unroll
        for (int ks = 0; ks < 8; ks++) {
            int kb = ks * 8;
            unsigned a[4][4], bf[4][2];
#pragma unroll
            for (int mf = 0; mf < 4; mf++) {
                int m = wm + mf * 16;
                a[mf][0] = Qs[(m + g) * QS + kb + tg];
                a[mf][1] = Qs[(m + g + 8) * QS + kb + tg];
                a[mf][2] = Qs[(m + g) * QS + kb + tg + 4];
                a[mf][3] = Qs[(m + g + 8) * QS + kb + tg + 4];
            }
#pragma unroll
            for (int nf = 0; nf < 4; nf++) {
                int n = wn + nf * 8;
                bf[nf][0] = Ks[(n + g) * QS + kb + tg];
                bf[nf][1] = Ks[(n + g) * QS + kb + tg + 4];
            }
#pragma unroll
            for (int mf = 0; mf < 4; mf++)
#pragma unroll
                for (int nf = 0; nf < 4; nf++)
                    mma_tf32(acc[mf][nf], a[mf], bf[nf]);
        }

        // p = exp(S/8) * inv ; write normalized attn; stage Ps for PV
#pragma unroll
        for (int mf = 0; mf < 4; mf++) {
#pragma unroll
            for (int nf = 0; nf < 4; nf++) {
                int m0 = wm + mf * 16 + g;
                int n0 = wn + nf * 8 + 2 * tg;
                float e0 = ex2f(acc[mf][nf][0] * C1F) * iA[mf];
                float e1 = ex2f(acc[mf][nf][1] * C1F) * iA[mf];
                float e2 = ex2f(acc[mf][nf][2] * C1F) * iB[mf];
                float e3 = ex2f(acc[mf][nf][3] * C1F) * iB[mf];
                *(float2*)(Az + (long)m0 * TT + kt * 128 + n0)       = make_float2(e0, e1);
                *(float2*)(Az + (long)(m0 + 8) * TT + kt * 128 + n0) = make_float2(e2, e3);
                uint2 u0 = { f2tf32(e0), f2tf32(e1) };
                uint2 u1 = { f2tf32(e2), f2tf32(e3) };
                *(uint2*)(&Ps[m0 * PS + n0])       = u0;
                *(uint2*)(&Ps[(m0 + 8) * PS + n0]) = u1;
            }
        }
        __syncthreads();

        // X += P @ V  (PV warp layout)
#pragma unroll
        for (int ks = 0; ks < 16; ks++) {
            int kb = ks * 8;
            unsigned a2[2][4], b2[4][2];
#pragma unroll
            for (int mf = 0; mf < 2; mf++) {
                int m = wm2 + mf * 16;
                a2[mf][0] = Ps[(m + g) * PS + kb + tg];
                a2[mf][1] = Ps[(m + g + 8) * PS + kb + tg];
                a2[mf][2] = Ps[(m + g) * PS + kb + tg + 4];
                a2[mf][3] = Ps[(m + g + 8) * PS + kb + tg + 4];
            }
#pragma unroll
            for (int nf = 0; nf < 4; nf++) {
                int n = wn2 + nf * 8;
                b2[nf][0] = Vs[(kb + tg) * VS + n + g];
                b2[nf][1] = Vs[(kb + tg + 4) * VS + n + g];
            }
#pragma unroll
            for (int mf = 0; mf < 2; mf++)
#pragma unroll
                for (int nf = 0; nf < 4; nf++)
                    mma_tf32(xacc[mf][nf], a2[mf], b2[nf]);
        }
        __syncthreads();
    }

    // X epilogue (already normalized)
#pragma unroll
    for (int mf = 0; mf < 2; mf++)
#pragma unroll
        for (int nf = 0; nf < 4; nf++) {
            int m0 = wm2 + mf * 16 + g;
            int n0 = wn2 + nf * 8 + 2 * tg;
            *(float2*)(Xz + (long)m0 * DD + n0) =
                make_float2(xacc[mf][nf][0], xacc[mf][nf][1]);
            *(float2*)(Xz + (long)(m0 + 8) * DD + n0) =
                make_float2(xacc[mf][nf][2], xacc[mf][nf][3]);
        }
}

#define FATTN2_SMEM ((128 * QS * 2 + 128 * VS + 128 * PS) * 4 + 128 * 4)

// =============================================================================
// residual + LayerNorm: y = LN(query + o) * gamma + beta ; one block per row
// =============================================================================
__global__ __launch_bounds__(256)
void resid_ln_k(const float* __restrict__ q, const float* __restrict__ o,
                const float* __restrict__ gamma, const float* __restrict__ beta,
                float* __restrict__ out)
{
    __shared__ float redA[8], redB[8];
    __shared__ float s_mu, s_rstd;

    long row = blockIdx.x;
    const float* qp = q + row * DD;
    const float* op = o + row * DD;
    float* yp = out + row * DD;
    int tid = threadIdx.x;

    float4 a = *(const float4*)(qp + tid * 4);
    float4 b = *(const float4*)(op + tid * 4);
    float4 y = make_float4(a.x + b.x, a.y + b.y, a.z + b.z, a.w + b.w);

    float s  = y.x + y.y + y.z + y.w;
    float s2 = y.x * y.x + y.y * y.y + y.z * y.z + y.w * y.w;
#pragma unroll
    for (int sh = 16; sh > 0; sh >>= 1) {
        s  += __shfl_xor_sync(0xffffffffu, s,  sh);
        s2 += __shfl_xor_sync(0xffffffffu, s2, sh);
    }
    if ((tid & 31) == 0) { redA[tid >> 5] = s; redB[tid >> 5] = s2; }
    __syncthreads();
    if (tid < 32) {
        float t  = redA[tid & 7];
        float t2 = redB[tid & 7];
#pragma unroll
        for (int sh = 4; sh > 0; sh >>= 1) {
            t  += __shfl_xor_sync(0xffffffffu, t,  sh);
            t2 += __shfl_xor_sync(0xffffffffu, t2, sh);
        }
        if (tid == 0) {
            float mu  = t / (float)DD;
            float var = t2 / (float)DD - mu * mu;
            s_mu = mu;
            s_rstd = rsqrtf(var + 1e-5f);
        }
    }
    __syncthreads();
    float mu = s_mu, rstd = s_rstd;

    float4 gm = *(const float4*)(gamma + tid * 4);
    float4 be = *(const float4*)(beta + tid * 4);
    float4 r;
    r.x = (y.x - mu) * rstd * gm.x + be.x;
    r.y = (y.y - mu) * rstd * gm.y + be.y;
    r.z = (y.z - mu) * rstd * gm.z + be.z;
    r.w = (y.w - mu) * rstd * gm.w + be.w;
    *(float4*)(yp + tid * 4) = r;
}

// =============================================================================
extern "C" void kernel_launch(void* const* d_in, const int* in_sizes, int n_in,
                              void* d_out, int out_size)
{
    const float* query = (const float*)d_in[0];
    const float* key   = (const float*)d_in[1];
    const float* value = (const float*)d_in[2];
    const float* Wq = (const float*)d_in[3];
    const float* bq = (const float*)d_in[4];
    const float* Wk = (const float*)d_in[5];
    const float* bk = (const float*)d_in[6];
    const float* Wv = (const float*)d_in[7];
    const float* bv = (const float*)d_in[8];
    const float* Wo = (const float*)d_in[9];
    const float* bo = (const float*)d_in[10];
    const float* gamma = (const float*)d_in[11];
    const float* beta  = (const float*)d_in[12];

    float* out = (float*)d_out;

    float *q, *k, *v, *x, *o, *attn_scr;
    float2* stats;
    cudaGetSymbolAddress((void**)&q, g_q);
    cudaGetSymbolAddress((void**)&k, g_k);
    cudaGetSymbolAddress((void**)&v, g_v);
    cudaGetSymbolAddress((void**)&x, g_x);
    cudaGetSymbolAddress((void**)&o, g_o);
    cudaGetSymbolAddress((void**)&stats, g_stats);
    cudaGetSymbolAddress((void**)&attn_scr, g_attn_scratch);

    const long y_elems    = (long)BB * TT * DD;
    const long attn_elems = (long)BB * HH * TT * TT;
    float* y_out = out;
    float* attn  = ((long)out_size >= y_elems + attn_elems) ? (out + y_elems)
                                                            : attn_scr;

    static int smem_set = 0;
    if (!smem_set) {
        cudaFuncSetAttribute(proj_qkv, cudaFuncAttributeMaxDynamicSharedMemorySize,
                             FPROJ_SMEM);
        cudaFuncSetAttribute(proj_o, cudaFuncAttributeMaxDynamicSharedMemorySize,
                             FPROJ_SMEM);
        cudaFuncSetAttribute(fstats, cudaFuncAttributeMaxDynamicSharedMemorySize,
                             FSTATS_SMEM);
        cudaFuncSetAttribute(fattn2, cudaFuncAttributeMaxDynamicSharedMemorySize,
                             FATTN2_SMEM);
        smem_set = 1;
    }

    dim3 tpb(256);

    // Q/K/V projections: ONE launch, fstats-structured GEMM body (BK=64)
    dim3 gqkv(DD / 128, BT / 128, 3);
    proj_qkv<<<gqkv, tpb, FPROJ_SMEM>>>(query, key, value, Wq, Wk, Wv,
                                        bq, bk, bv, q, k, v);

    // pass 1: row stats (2 CTAs/SM)
    dim3 gf(1, TT / 128, BB * HH);
    fstats<<<gf, tpb, FSTATS_SMEM>>>(q, k, stats);

    // pass 2: normalized attn write + PV (round-8 structure)
    fattn2<<<gf, tpb, FATTN2_SMEM>>>(q, k, v, stats, attn, x);

    // output projection
    dim3 gproj(DD / 128, BT / 128, 1);
    proj_o<<<gproj, tpb, FPROJ_SMEM>>>(x, Wo, bo, o);

    // residual + LayerNorm -> y
    resid_ln_k<<<BT, tpb>>>(query, o, gamma, beta, y_out);
}